// round 2
// baseline (speedup 1.0000x reference)
#include <cuda_runtime.h>

#define BATCH 4
#define NPTS 8192
#define THREADS 128
#define QPT 8
#define TILE_Q (THREADS * QPT)        // 1024
#define TILE_T 256
#define NSEG (NPTS / TILE_T)          // 32
#define NQT  (NPTS / TILE_Q)          // 8
#define NBLK (NQT * BATCH * 2 * NSEG) // 2048
#define TOTQ (2 * BATCH * NPTS)       // 65536
#define FIN_THREADS 256
#define FIN_BLOCKS (TOTQ / FIN_THREADS) // 256

typedef unsigned long long ull;

// Scratch (zero-init at module load; kernels restore zeros for graph replay).
__device__ unsigned g_key[TOTQ];       // key = ~monotone(f); min f == max key; 0 is identity
__device__ float    g_bsum[FIN_BLOCKS];
__device__ unsigned g_count;

__device__ __forceinline__ ull pack2(float a, float b) {
    ull r;
    asm("mov.b64 %0, {%1, %2};" : "=l"(r) : "f"(a), "f"(b));
    return r;
}
// Monotone float->uint, then inverted so that 0 acts as "+infinity" under atomicMax.
__device__ __forceinline__ unsigned enckey(float f) {
    unsigned u = __float_as_uint(f);
    u = (u & 0x80000000u) ? ~u : (u | 0x80000000u);
    return ~u;
}
__device__ __forceinline__ float deckey(unsigned k) {
    unsigned u = ~k;
    return __uint_as_float((u & 0x80000000u) ? (u & 0x7FFFFFFFu) : ~u);
}

// One packed step: d2(lo,hi) = qx*n0 + qy*n1 + qz*n2 + cc (2 targets), then
// two independent scalar mins (FMNMX is alu-pipe on sm_103a -> overlaps FFMA2).
__device__ __forceinline__ void step(float& ma, float& mb,
                                     ull qx, ull qy, ull qz,
                                     ull n0, ull n1, ull n2, ull cc) {
    asm("{\n\t"
        ".reg .b64 t;\n\t"
        ".reg .f32 lo, hi;\n\t"
        "fma.rn.f32x2 t, %2, %5, %8;\n\t"
        "fma.rn.f32x2 t, %3, %6, t;\n\t"
        "fma.rn.f32x2 t, %4, %7, t;\n\t"
        "mov.b64 {lo, hi}, t;\n\t"
        "min.f32 %0, %0, lo;\n\t"
        "min.f32 %1, %1, hi;\n\t"
        "}"
        : "+f"(ma), "+f"(mb)
        : "l"(qx), "l"(qy), "l"(qz), "l"(n0), "l"(n1), "l"(n2), "l"(cc));
}

__global__ __launch_bounds__(THREADS)
void chamfer_main(const float* __restrict__ p1, const float* __restrict__ p2) {
    const int bx  = blockIdx.x;
    const int seg = bx >> 6;          // 0..31 target segment
    const int r   = bx & 63;
    const int qt  = r & 7;            // query tile
    const int b   = (r >> 3) & 3;     // batch
    const int dir = r >> 5;           // 0: q=p1,t=p2 ; 1: q=p2,t=p1
    const float* __restrict__ Q = dir ? p2 : p1;
    const float* __restrict__ T = dir ? p1 : p2;

    // Interleaved target tile: per pair j -> [n0|n1|n2|cc] packed f32x2, 32B.
    __shared__ __align__(16) ull s_t[TILE_T / 2][4];

    const float* tb = T + ((size_t)b * NPTS + (size_t)seg * TILE_T) * 3;
    {
        const int i = threadIdx.x;    // exactly TILE_T/2 = 128 pairs
        float a0 = tb[6 * i + 0], a1 = tb[6 * i + 1], a2 = tb[6 * i + 2];
        float c0 = tb[6 * i + 3], c1 = tb[6 * i + 4], c2 = tb[6 * i + 5];
        ulonglong2* d = (ulonglong2*)s_t[i];
        d[0] = make_ulonglong2(pack2(-2.0f * a0, -2.0f * c0),
                               pack2(-2.0f * a1, -2.0f * c1));
        d[1] = make_ulonglong2(pack2(-2.0f * a2, -2.0f * c2),
                               pack2(a0 * a0 + a1 * a1 + a2 * a2,
                                     c0 * c0 + c1 * c1 + c2 * c2));
    }

    // Each thread owns QPT query points, duplicated into both f32x2 halves.
    ull qx[QPT], qy[QPT], qz[QPT];
    float ma[QPT], mb[QPT];
    const int qbase = qt * TILE_Q + threadIdx.x;
#pragma unroll
    for (int k = 0; k < QPT; k++) {
        const float* qp = Q + ((size_t)b * NPTS + qbase + k * THREADS) * 3;
        float x0 = qp[0], x1 = qp[1], x2 = qp[2];
        qx[k] = pack2(x0, x0);
        qy[k] = pack2(x1, x1);
        qz[k] = pack2(x2, x2);
        ma[k] = 3.4e38f;
        mb[k] = 3.4e38f;
    }
    __syncthreads();

    const ulonglong2* sm = (const ulonglong2*)&s_t[0][0];
#pragma unroll 2
    for (int j = 0; j < TILE_T / 2; j++) {
        ulonglong2 v0 = sm[2 * j];       // (n0, n1)  LDS.128 broadcast
        ulonglong2 v1 = sm[2 * j + 1];   // (n2, cc)  LDS.128 broadcast
#pragma unroll
        for (int k = 0; k < QPT; k++)
            step(ma[k], mb[k], qx[k], qy[k], qz[k], v0.x, v0.y, v1.x, v1.y);
    }

    unsigned* gm = g_key + ((size_t)dir * BATCH + b) * NPTS;
#pragma unroll
    for (int k = 0; k < QPT; k++)
        atomicMax(&gm[qbase + k * THREADS], enckey(fminf(ma[k], mb[k])));
}

__global__ __launch_bounds__(FIN_THREADS)
void chamfer_finish(const float* __restrict__ p1, const float* __restrict__ p2,
                    float* __restrict__ out) {
    const int gid = blockIdx.x * FIN_THREADS + threadIdx.x;   // over 65536
    const int dir = gid >> 15;
    const int rem = gid & 32767;
    const float* Q = dir ? p2 : p1;
    const float* qp = Q + (size_t)rem * 3;
    float x0 = qp[0], x1 = qp[1], x2 = qp[2];
    float v = fmaf(x0, x0, fmaf(x1, x1, x2 * x2)) + deckey(g_key[gid]);
    g_key[gid] = 0u;                  // reset scratch for next graph replay

    // block reduction
    __shared__ float sred[8];
    __shared__ bool s_last;
#pragma unroll
    for (int o = 16; o; o >>= 1) v += __shfl_down_sync(0xffffffffu, v, o);
    if ((threadIdx.x & 31) == 0) sred[threadIdx.x >> 5] = v;
    __syncthreads();
    if (threadIdx.x == 0) {
        float w = 0.0f;
#pragma unroll
        for (int i = 0; i < 8; i++) w += sred[i];
        g_bsum[blockIdx.x] = w;
        __threadfence();
        unsigned t = atomicAdd(&g_count, 1u);
        s_last = (t == FIN_BLOCKS - 1);
    }
    __syncthreads();

    if (s_last) {                      // last block reduces all partials
        __threadfence();
        float w = g_bsum[threadIdx.x]; // FIN_BLOCKS == FIN_THREADS == 256
#pragma unroll
        for (int o = 16; o; o >>= 1) w += __shfl_down_sync(0xffffffffu, w, o);
        if ((threadIdx.x & 31) == 0) sred[threadIdx.x >> 5] = w;
        __syncthreads();
        if (threadIdx.x == 0) {
            float tot = 0.0f;
#pragma unroll
            for (int i = 0; i < 8; i++) tot += sred[i];
            out[0] = tot;
            g_count = 0u;              // reset for next graph replay
        }
    }
}

extern "C" void kernel_launch(void* const* d_in, const int* in_sizes, int n_in,
                              void* d_out, int out_size) {
    const float* p1 = (const float*)d_in[0];
    const float* p2 = (const float*)d_in[1];
    float* out = (float*)d_out;

    chamfer_main<<<NBLK, THREADS>>>(p1, p2);
    chamfer_finish<<<FIN_BLOCKS, FIN_THREADS>>>(p1, p2, out);
}